// round 1
// baseline (speedup 1.0000x reference)
#include <cuda_runtime.h>
#include <math.h>

// Cone-beam forward projection.
// vol: [B=2, Z=96, Y=96, X=96] float32, ZYX layout.
// out: [B=2, A=48, V=96, U=96] float32.

#define NZ 96
#define NY 96
#define NX 96
#define NV 96
#define NU 96
#define NA 48
#define NS 96

#define DSO 500.0f
#define DSD 1000.0f
#define DDET 2.0f

// R = 0.5*sqrt(3*96^2) ; step = 2R/NS ; t0 = DSO - R  (computed in double, truncated)
#define R_SPH 83.138438763306072f
#define STEP 1.7320508075688772f
#define T0 416.86156123669393f

#define VOL_N (NZ * NY * NX)     // 884736
#define SX 1
#define SY NX                    // 96
#define SZ (NX * NY)             // 9216

__global__ void __launch_bounds__(256) fp_kernel(const float* __restrict__ vol,
                                                 float* __restrict__ out) {
    int idx = blockIdx.x * blockDim.x + threadIdx.x;
    // total = 2 * 48 * 96 * 96 = 884736
    int u = idx % NU;
    int v = (idx / NU) % NV;
    int a = (idx / (NU * NV)) % NA;
    int b = idx / (NU * NV * NA);

    float theta = (float)a * (6.2831853071795864769f / (float)NA);
    float s, c;
    __sincosf(theta, &s, &c);
    // use accurate versions to stay close to reference
    s = sinf(theta);
    c = cosf(theta);

    float srcx = DSO * c;
    float srcy = DSO * s;
    // srcz = 0

    float uu = ((float)u - (NU - 1) * 0.5f) * DDET;
    float vv = ((float)v - (NV - 1) * 0.5f) * DDET;

    // detector pixel world position
    float px = -(DSD - DSO) * c - uu * s;
    float py = -(DSD - DSO) * s + uu * c;
    float pz = vv;

    float dx = px - srcx;
    float dy = py - srcy;
    float dz = pz;  // - 0
    float inv = rsqrtf(fmaf(dx, dx, fmaf(dy, dy, dz * dz)));
    dx *= inv; dy *= inv; dz *= inv;

    const float* volb = vol + (long)b * VOL_N;

    float acc = 0.0f;

    #pragma unroll 4
    for (int i = 0; i < NS; i++) {
        float t = fmaf((float)i + 0.5f, STEP, T0);
        // world position -> voxel coords (DV=1, center offset 47.5)
        float x = fmaf(dx, t, srcx) + (NX - 1) * 0.5f;
        float y = fmaf(dy, t, srcy) + (NY - 1) * 0.5f;
        float z = fmaf(dz, t, 0.0f) + (NZ - 1) * 0.5f;

        bool valid = (x >= 0.0f) & (x <= (float)(NX - 1)) &
                     (y >= 0.0f) & (y <= (float)(NY - 1)) &
                     (z >= 0.0f) & (z <= (float)(NZ - 1));
        if (valid) {
            int x0 = min((int)x, NX - 2);   // x >= 0, trunc == floor
            int y0 = min((int)y, NY - 2);
            int z0 = min((int)z, NZ - 2);
            float fx = x - (float)x0;
            float fy = y - (float)y0;
            float fz = z - (float)z0;

            const float* p = volb + z0 * SZ + y0 * SY + x0;
            float v000 = __ldg(p);
            float v001 = __ldg(p + 1);
            float v010 = __ldg(p + SY);
            float v011 = __ldg(p + SY + 1);
            float v100 = __ldg(p + SZ);
            float v101 = __ldg(p + SZ + 1);
            float v110 = __ldg(p + SZ + SY);
            float v111 = __ldg(p + SZ + SY + 1);

            float c00 = fmaf(fx, v001 - v000, v000);
            float c01 = fmaf(fx, v011 - v010, v010);
            float c10 = fmaf(fx, v101 - v100, v100);
            float c11 = fmaf(fx, v111 - v110, v110);
            float c0  = fmaf(fy, c01 - c00, c00);
            float c1  = fmaf(fy, c11 - c10, c10);
            acc += fmaf(fz, c1 - c0, c0);
        }
    }

    out[idx] = acc * STEP;
}

extern "C" void kernel_launch(void* const* d_in, const int* in_sizes, int n_in,
                              void* d_out, int out_size) {
    const float* vol = (const float*)d_in[0];
    float* out = (float*)d_out;
    int total = 2 * NA * NV * NU;   // 884736
    int threads = 256;
    int blocks = (total + threads - 1) / threads;
    fp_kernel<<<blocks, threads>>>(vol, out);
}

// round 2
// speedup vs baseline: 1.7048x; 1.7048x over previous
#include <cuda_runtime.h>
#include <math.h>

// Cone-beam forward projection, batch-interleaved + z-pair-duplicated volume.
// vol in: [B=2, Z=96, Y=96, X=96] float32 (ZYX).
// out:    [B=2, A=48, V=96, U=96] float32.

#define NZ 96
#define NY 96
#define NX 96
#define NV 96
#define NU 96
#define NA 48
#define NS 96

#define DSO 500.0f
#define DSD 1000.0f
#define DDET 2.0f

#define STEP 1.7320508075688772f
#define T0   416.86156123669393f

#define VOL_N (NZ * NY * NX)     // 884736
#define SY NX                    // 96
#define SZ (NX * NY)             // 9216

// g_vol4[z][y][x] = (b0[z][y][x], b1[z][y][x], b0[z+1][y][x], b1[z+1][y][x])
__device__ float4 g_vol4[VOL_N];

__global__ void __launch_bounds__(256) prep_kernel(const float* __restrict__ vol) {
    int i = blockIdx.x * blockDim.x + threadIdx.x;
    if (i >= VOL_N) return;
    int z = i / SZ;
    int ip = (z < NZ - 1) ? (i + SZ) : i;     // z+1 row (z=95 never read by interp)
    g_vol4[i] = make_float4(vol[i], vol[VOL_N + i], vol[ip], vol[VOL_N + ip]);
}

__global__ void __launch_bounds__(256) fp_kernel(float* __restrict__ out) {
    int idx = blockIdx.x * blockDim.x + threadIdx.x;
    // total = 48 * 96 * 96 = 442368 (one thread serves both batches)
    int u = idx % NU;
    int v = (idx / NU) % NV;
    int a = idx / (NU * NV);

    float theta = (float)a * (6.2831853071795864769f / (float)NA);
    float s = sinf(theta);
    float c = cosf(theta);

    float srcx = DSO * c;
    float srcy = DSO * s;

    float uu = ((float)u - (NU - 1) * 0.5f) * DDET;
    float vv = ((float)v - (NV - 1) * 0.5f) * DDET;

    float px = -(DSD - DSO) * c - uu * s;
    float py = -(DSD - DSO) * s + uu * c;
    float pz = vv;

    float dx = px - srcx;
    float dy = py - srcy;
    float dz = pz;
    float inv = rsqrtf(fmaf(dx, dx, fmaf(dy, dy, dz * dz)));
    dx *= inv; dy *= inv; dz *= inv;

    // ray/box slab test in world coords, box = [-47.5, 47.5]^3
    const float H = 47.5f;
    float ix_ = 1.0f / dx, iy_ = 1.0f / dy, iz_ = 1.0f / dz;
    float tx1 = (-H - srcx) * ix_, tx2 = (H - srcx) * ix_;
    float ty1 = (-H - srcy) * iy_, ty2 = (H - srcy) * iy_;
    float tz1 = (-H) * iz_,        tz2 = (H) * iz_;
    float tmin = fmaxf(fmaxf(fminf(tx1, tx2), fminf(ty1, ty2)), fminf(tz1, tz2));
    float tmax = fminf(fminf(fmaxf(tx1, tx2), fmaxf(ty1, ty2)), fmaxf(tz1, tz2));

    int i0 = 0, i1 = 0;
    if (tmax > tmin) {
        // sample i has t = T0 + (i+0.5)*STEP ; pad by 1 for fp safety
        i0 = max(0, (int)floorf((tmin - T0) / STEP - 0.5f) - 1);
        i1 = min(NS, (int)ceilf((tmax - T0) / STEP - 0.5f) + 2);
    }

    float acc0 = 0.0f, acc1 = 0.0f;

    #pragma unroll 4
    for (int i = i0; i < i1; i++) {
        float t = fmaf((float)i + 0.5f, STEP, T0);
        float x = fmaf(dx, t, srcx) + (NX - 1) * 0.5f;
        float y = fmaf(dy, t, srcy) + (NY - 1) * 0.5f;
        float z = dz * t + (NZ - 1) * 0.5f;

        bool valid = (x >= 0.0f) & (x <= (float)(NX - 1)) &
                     (y >= 0.0f) & (y <= (float)(NY - 1)) &
                     (z >= 0.0f) & (z <= (float)(NZ - 1));
        if (valid) {
            int x0 = min((int)x, NX - 2);
            int y0 = min((int)y, NY - 2);
            int z0 = min((int)z, NZ - 2);
            float fx = x - (float)x0;
            float fy = y - (float)y0;
            float fz = z - (float)z0;

            const float4* p = g_vol4 + (z0 * SZ + y0 * SY + x0);
            float4 q00 = __ldg(p);            // (b0@z0, b1@z0, b0@z1, b1@z1) at (y0,x0)
            float4 q01 = __ldg(p + 1);        // (y0,x1)
            float4 q10 = __ldg(p + SY);       // (y1,x0)
            float4 q11 = __ldg(p + SY + 1);   // (y1,x1)

            // bilinear weights in (x,y)
            float wd = fx * fy;
            float wb = fx - wd;
            float wc = fy - wd;
            float wa = 1.0f - fx - wc;

            // batch 0
            float b0z0 = fmaf(q00.x, wa, fmaf(q01.x, wb, fmaf(q10.x, wc, q11.x * wd)));
            float b0z1 = fmaf(q00.z, wa, fmaf(q01.z, wb, fmaf(q10.z, wc, q11.z * wd)));
            acc0 += fmaf(fz, b0z1 - b0z0, b0z0);
            // batch 1
            float b1z0 = fmaf(q00.y, wa, fmaf(q01.y, wb, fmaf(q10.y, wc, q11.y * wd)));
            float b1z1 = fmaf(q00.w, wa, fmaf(q01.w, wb, fmaf(q10.w, wc, q11.w * wd)));
            acc1 += fmaf(fz, b1z1 - b1z0, b1z0);
        }
    }

    out[idx] = acc0 * STEP;
    out[idx + NA * NV * NU] = acc1 * STEP;
}

extern "C" void kernel_launch(void* const* d_in, const int* in_sizes, int n_in,
                              void* d_out, int out_size) {
    const float* vol = (const float*)d_in[0];
    float* out = (float*)d_out;

    {
        int threads = 256;
        int blocks = (VOL_N + threads - 1) / threads;
        prep_kernel<<<blocks, threads>>>(vol);
    }
    {
        int total = NA * NV * NU;   // 442368
        int threads = 256;
        int blocks = (total + threads - 1) / threads;
        fp_kernel<<<blocks, threads>>>(out);
    }
}

// round 3
// speedup vs baseline: 2.8630x; 1.6794x over previous
#include <cuda_runtime.h>
#include <cuda_fp16.h>
#include <math.h>

// Cone-beam forward projection.
// Volume repacked to fp16, batch+z+x interleaved:
//   g_vol8[z][y][x] = 8 halves: (b0,b1) x (z0,z1) x (x0,x1)  -> one 16B cell.
// Per sample: 2 aligned LDG.128 (rows y0, y1) give all 16 corner values
// for BOTH batches. Lerp + accumulation in fp32.
// vol in: [B=2, Z=96, Y=96, X=96] fp32. out: [B=2, A=48, V=96, U=96] fp32.

#define NZ 96
#define NY 96
#define NX 96
#define NV 96
#define NU 96
#define NA 48
#define NS 96

#define DSO 500.0f
#define DSD 1000.0f
#define DDET 2.0f

#define STEP 1.7320508075688772f
#define T0   416.86156123669393f

#define VOL_N (NZ * NY * NX)     // 884736
#define SY NX                    // 96
#define SZ (NX * NY)             // 9216

__device__ uint4 g_vol8[VOL_N];  // 14.2 MB

static __device__ __forceinline__ unsigned h2u(__half2 h) {
    union { __half2 h; unsigned u; } cvt; cvt.h = h; return cvt.u;
}
static __device__ __forceinline__ __half2 u2h(unsigned u) {
    union { unsigned u; __half2 h; } cvt; cvt.u = u; return cvt.h;
}

__global__ void __launch_bounds__(256) prep_kernel(const float* __restrict__ vol) {
    int i = blockIdx.x * blockDim.x + threadIdx.x;
    if (i >= VOL_N) return;
    int z = i / SZ;
    int x = i % NX;
    int xp = (x < NX - 1) ? 1 : 0;     // x=95 cell never read by interp (x0<=94)
    int zp = (z < NZ - 1) ? SZ : 0;    // z=95 cell never read

    const float* b0 = vol;
    const float* b1 = vol + VOL_N;

    uint4 q;
    q.x = h2u(__floats2half2_rn(b0[i],           b1[i]));            // z0,x0
    q.y = h2u(__floats2half2_rn(b0[i + xp],      b1[i + xp]));       // z0,x1
    q.z = h2u(__floats2half2_rn(b0[i + zp],      b1[i + zp]));       // z1,x0
    q.w = h2u(__floats2half2_rn(b0[i + zp + xp], b1[i + zp + xp]));  // z1,x1
    g_vol8[i] = q;
}

__global__ void __launch_bounds__(256) fp_kernel(float* __restrict__ out) {
    int idx = blockIdx.x * blockDim.x + threadIdx.x;
    // 48 * 96 * 96 = 442368 threads; each serves both batches
    int u = idx % NU;
    int v = (idx / NU) % NV;
    int a = idx / (NU * NV);

    float theta = (float)a * (6.2831853071795864769f / (float)NA);
    float s = sinf(theta);
    float c = cosf(theta);

    float srcx = DSO * c;
    float srcy = DSO * s;

    float uu = ((float)u - (NU - 1) * 0.5f) * DDET;
    float vv = ((float)v - (NV - 1) * 0.5f) * DDET;

    float px = -(DSD - DSO) * c - uu * s;
    float py = -(DSD - DSO) * s + uu * c;
    float pz = vv;

    float dx = px - srcx;
    float dy = py - srcy;
    float dz = pz;
    float inv = rsqrtf(fmaf(dx, dx, fmaf(dy, dy, dz * dz)));
    dx *= inv; dy *= inv; dz *= inv;

    // ray/box slab test, box = [-47.5, 47.5]^3 world
    const float H = 47.5f;
    float ix_ = 1.0f / dx, iy_ = 1.0f / dy, iz_ = 1.0f / dz;
    float tx1 = (-H - srcx) * ix_, tx2 = (H - srcx) * ix_;
    float ty1 = (-H - srcy) * iy_, ty2 = (H - srcy) * iy_;
    float tz1 = (-H) * iz_,        tz2 = (H) * iz_;
    float tmin = fmaxf(fmaxf(fminf(tx1, tx2), fminf(ty1, ty2)), fminf(tz1, tz2));
    float tmax = fminf(fminf(fmaxf(tx1, tx2), fmaxf(ty1, ty2)), fmaxf(tz1, tz2));

    int i0 = 0, i1 = 0;
    if (tmax > tmin) {
        i0 = max(0, (int)floorf((tmin - T0) / STEP - 0.5f) - 1);
        i1 = min(NS, (int)ceilf((tmax - T0) / STEP - 0.5f) + 2);
    }

    float acc0 = 0.0f, acc1 = 0.0f;

    #pragma unroll 4
    for (int i = i0; i < i1; i++) {
        float t = fmaf((float)i + 0.5f, STEP, T0);
        float x = fmaf(dx, t, srcx) + (NX - 1) * 0.5f;
        float y = fmaf(dy, t, srcy) + (NY - 1) * 0.5f;
        float z = dz * t + (NZ - 1) * 0.5f;

        bool valid = (x >= 0.0f) & (x <= (float)(NX - 1)) &
                     (y >= 0.0f) & (y <= (float)(NY - 1)) &
                     (z >= 0.0f) & (z <= (float)(NZ - 1));
        if (valid) {
            int x0 = min((int)x, NX - 2);
            int y0 = min((int)y, NY - 2);
            int z0 = min((int)z, NZ - 2);
            float fx = x - (float)x0;
            float fy = y - (float)y0;
            float fz = z - (float)z0;

            const uint4* p = g_vol8 + (z0 * SZ + y0 * SY + x0);
            uint4 r0 = __ldg(p);        // row y0: (z0x0, z0x1, z1x0, z1x1) batch-pairs
            uint4 r1 = __ldg(p + SY);   // row y1

            // bilinear weights in (x,y): wa=(1-fx)(1-fy) wb=fx(1-fy) wc=(1-fx)fy wd=fx*fy
            float wd = fx * fy;
            float wb = fx - wd;
            float wc = fy - wd;
            float wa = 1.0f - fx - wc;

            float2 a0 = __half22float2(u2h(r0.x));  // y0 z0 x0 : (b0,b1)
            float2 a1 = __half22float2(u2h(r0.y));  // y0 z0 x1
            float2 a2 = __half22float2(u2h(r0.z));  // y0 z1 x0
            float2 a3 = __half22float2(u2h(r0.w));  // y0 z1 x1
            float2 b0_ = __half22float2(u2h(r1.x)); // y1 z0 x0
            float2 b1_ = __half22float2(u2h(r1.y)); // y1 z0 x1
            float2 b2_ = __half22float2(u2h(r1.z)); // y1 z1 x0
            float2 b3_ = __half22float2(u2h(r1.w)); // y1 z1 x1

            // z0 plane bilinear (batch0 = .x, batch1 = .y)
            float p0x = fmaf(a0.x, wa, fmaf(a1.x, wb, fmaf(b0_.x, wc, b1_.x * wd)));
            float p0y = fmaf(a0.y, wa, fmaf(a1.y, wb, fmaf(b0_.y, wc, b1_.y * wd)));
            // z1 plane bilinear
            float p1x = fmaf(a2.x, wa, fmaf(a3.x, wb, fmaf(b2_.x, wc, b3_.x * wd)));
            float p1y = fmaf(a2.y, wa, fmaf(a3.y, wb, fmaf(b2_.y, wc, b3_.y * wd)));

            acc0 += fmaf(fz, p1x - p0x, p0x);
            acc1 += fmaf(fz, p1y - p0y, p0y);
        }
    }

    out[idx] = acc0 * STEP;
    out[idx + NA * NV * NU] = acc1 * STEP;
}

extern "C" void kernel_launch(void* const* d_in, const int* in_sizes, int n_in,
                              void* d_out, int out_size) {
    const float* vol = (const float*)d_in[0];
    float* out = (float*)d_out;

    {
        int threads = 256;
        int blocks = (VOL_N + threads - 1) / threads;
        prep_kernel<<<blocks, threads>>>(vol);
    }
    {
        int total = NA * NV * NU;   // 442368
        int threads = 256;
        int blocks = (total + threads - 1) / threads;
        fp_kernel<<<blocks, threads>>>(out);
    }
}